// round 14
// baseline (speedup 1.0000x reference)
#include <cuda_runtime.h>
#include <cuda_bf16.h>
#include <cuda_fp16.h>
#include <stdint.h>
#include <math.h>

// ---------------------------------------------------------------------------
// Problem constants
// ---------------------------------------------------------------------------
#define NUM_CLASSES 10
#define DD     64
#define MAXB   1024
#define NE_PAD 50048           // 391 tiles of 128
#define GAMMA  1.0f
#define EPS    1e-12f

// Hybrid: per 128x128 tile, cols 0-95 = bf16 HMMA warps 0-5 (warp tile 64x32,
// the R8-proven shape); cols 96-127 = f16 HFMA2 SIMT warps 6-7.
#define TM 128
#define TN 128
#define TNT 96
#define GCOLS 37               // grid = 8 x 37 = 296 CTAs = 2/SM, one wave
#define ROWB 144               // smem row stride (64 x 2B + 16 pad)

#define SM_ABF 0                       // A bf16 (MMA)          18432
#define SM_AF  18432                   // A f16  (SIMT, swizzled)
#define SM_B0  36864                   // B buf0 (row<96 bf16, >=96 f16 swiz)
#define SM_B1  55296
#define SM_TOT 73728

#define MAXSURV (1u * 1024u * 1024u)

// ---------------------------------------------------------------------------
// Scratch (__device__ globals; no cudaMalloc allowed)
// ---------------------------------------------------------------------------
__device__ uint16_t g_e16[(size_t)NE_PAD * DD];  // (r%128)<96: bf16, else f16
__device__ uint16_t g_xbf[(size_t)MAXB * DD];
__device__ uint16_t g_xf [(size_t)MAXB * DD];
__device__ float g_e2[NE_PAD];
__device__ float g_x2[MAXB];
__device__ float g_class[MAXB * NUM_CLASSES];
__device__ float g_beta;
__device__ unsigned g_nsurv, g_done;
__device__ unsigned g_surv[MAXSURV];

// ---------------------------------------------------------------------------
// PTX helpers (baseline ISA only)
// ---------------------------------------------------------------------------
__device__ __forceinline__ uint32_t smem_to_u32(const void* p) {
    uint32_t a;
    asm("{ .reg .u64 t; cvta.to.shared.u64 t, %1; cvt.u32.u64 %0, t; }"
        : "=r"(a) : "l"(p));
    return a;
}
__device__ __forceinline__ void ldsm_x4(uint32_t* r, uint32_t addr) {
    asm volatile("ldmatrix.sync.aligned.m8n8.x4.shared.b16 {%0,%1,%2,%3}, [%4];"
                 : "=r"(r[0]), "=r"(r[1]), "=r"(r[2]), "=r"(r[3]) : "r"(addr));
}
__device__ __forceinline__ void ldsm_x2(uint32_t* r, uint32_t addr) {
    asm volatile("ldmatrix.sync.aligned.m8n8.x2.shared.b16 {%0,%1}, [%2];"
                 : "=r"(r[0]), "=r"(r[1]) : "r"(addr));
}
__device__ __forceinline__ void mma_bf16(float* c, const uint32_t* a,
                                         const uint32_t* b) {
    asm volatile(
        "mma.sync.aligned.m16n8k16.row.col.f32.bf16.bf16.f32 "
        "{%0,%1,%2,%3}, {%4,%5,%6,%7}, {%8,%9}, {%0,%1,%2,%3};"
        : "+f"(c[0]), "+f"(c[1]), "+f"(c[2]), "+f"(c[3])
        : "r"(a[0]), "r"(a[1]), "r"(a[2]), "r"(a[3]), "r"(b[0]), "r"(b[1]));
}
__device__ __forceinline__ void cp_async16(uint32_t dst, const void* src) {
    asm volatile("cp.async.cg.shared.global [%0], [%1], 16;"
                 :: "r"(dst), "l"(src) : "memory");
}
__device__ __forceinline__ void cp_commit() {
    asm volatile("cp.async.commit_group;" ::: "memory");
}
template <int N>
__device__ __forceinline__ void cp_wait() {
    asm volatile("cp.async.wait_group %0;" :: "n"(N) : "memory");
}
__device__ __forceinline__ void lds64(uint32_t* r, uint32_t addr) {
    asm volatile("ld.shared.v2.u32 {%0,%1}, [%2];"
                 : "=r"(r[0]), "=r"(r[1]) : "r"(addr));
}
__device__ __forceinline__ void push_surv(int row, int col) {
    unsigned q = atomicAdd(&g_nsurv, 1u);
    if (q < MAXSURV) g_surv[q] = ((unsigned)row << 16) | (unsigned)col;
}

// ---------------------------------------------------------------------------
// Prep: dual-dtype conversion, exact L2 norms, beta, zero bins.
// 4 threads/row, 16 floats each (the measured-faster R7 shape).
// ---------------------------------------------------------------------------
__global__ void prep_kernel(const float* __restrict__ x,
                            const float* __restrict__ ex,
                            const float* __restrict__ beta_raw,
                            int B, int NE) {
    const int t = threadIdx.x;
    const int gid = blockIdx.x * 256 + t;
    if (gid < MAXB * NUM_CLASSES) g_class[gid] = 0.f;
    if (gid == 0) {
        float br = beta_raw[0];
        g_beta = (br > 20.f) ? br : log1pf(expf(br));
        g_nsurv = 0u;
        g_done  = 0u;
    }
    const int R = blockIdx.x * 64 + (t >> 2);
    const int part = t & 3;          // 16-float segment
    bool is_x = false;
    int outr = R;
    const float* src = nullptr;
    if (R < NE_PAD) {
        if (R < NE) src = ex + (size_t)R * DD + part * 16;
    } else {
        int xr = R - NE_PAD;
        if (xr >= MAXB) return;
        is_x = true; outr = xr;
        if (xr < B) src = x + (size_t)xr * DD + part * 16;
    }
    float v[16];
    float s = 0.f;
    if (src) {
        #pragma unroll
        for (int q = 0; q < 4; q++) {
            float4 f = ((const float4*)src)[q];
            v[4*q+0] = f.x; v[4*q+1] = f.y; v[4*q+2] = f.z; v[4*q+3] = f.w;
            s += f.x*f.x + f.y*f.y + f.z*f.z + f.w*f.w;
        }
    } else {
        #pragma unroll
        for (int q = 0; q < 16; q++) v[q] = 0.f;
    }
    s += __shfl_xor_sync(0xFFFFFFFFu, s, 1);
    s += __shfl_xor_sync(0xFFFFFFFFu, s, 2);
    if (is_x) {
        alignas(16) uint16_t hb[16], hf[16];
        #pragma unroll
        for (int q = 0; q < 16; q++) {
            __nv_bfloat16 b16 = __float2bfloat16(v[q]);
            __half h16 = __float2half_rn(v[q]);
            hb[q] = *(uint16_t*)&b16;
            hf[q] = *(uint16_t*)&h16;
        }
        uint16_t* d1 = g_xbf + (size_t)outr * DD + part * 16;
        uint16_t* d2 = g_xf  + (size_t)outr * DD + part * 16;
        ((uint4*)d1)[0] = ((uint4*)hb)[0];  ((uint4*)d1)[1] = ((uint4*)hb)[1];
        ((uint4*)d2)[0] = ((uint4*)hf)[0];  ((uint4*)d2)[1] = ((uint4*)hf)[1];
        if (part == 0) g_x2[outr] = (outr < B) ? s : 0.f;
    } else {
        const bool use_bf = ((R & 127) < TNT);
        alignas(16) uint16_t hh[16];
        #pragma unroll
        for (int q = 0; q < 16; q++) {
            if (use_bf) {
                __nv_bfloat16 b16 = __float2bfloat16(v[q]);
                hh[q] = *(uint16_t*)&b16;
            } else {
                __half h16 = __float2half_rn(v[q]);
                hh[q] = *(uint16_t*)&h16;
            }
        }
        uint16_t* d = g_e16 + (size_t)outr * DD + part * 16;
        ((uint4*)d)[0] = ((uint4*)hh)[0];  ((uint4*)d)[1] = ((uint4*)hh)[1];
        if (part == 0) g_e2[outr] = (outr < NE) ? s : 3.0e8f;
    }
}

// ---------------------------------------------------------------------------
// Main: hybrid filter GEMM (tensor + fma pipes via warp-role split).
// ---------------------------------------------------------------------------
__global__ void __launch_bounds__(256, 2)
exemplar_hybrid_kernel(int B, int NE) {
    extern __shared__ char smem[];
    const uint32_t base = smem_to_u32(smem);
    const uint32_t sAbf = base + SM_ABF;
    const uint32_t sAf  = base + SM_AF;
    const uint32_t sbU[2] = { base + SM_B0, base + SM_B1 };

    const int t = threadIdx.x;
    const int wid = t >> 5, lane = t & 31;
    const int bm = blockIdx.y * TM;
    const int NT = (NE + TN - 1) / TN;

    // A tiles: bf16 plain (ldsm layout) + f16 chunk-swizzled for SIMT.
    for (int i = t; i < TM * 8; i += 256) {
        int r = i >> 3, c = i & 7;
        *(uint4*)(smem + SM_ABF + r * ROWB + c * 16) =
            *(const uint4*)(g_xbf + (size_t)(bm + r) * DD + c * 8);
        int dc = c ^ ((r >> 3) & 7);
        *(uint4*)(smem + SM_AF + r * ROWB + dc * 16) =
            *(const uint4*)(g_xf + (size_t)(bm + r) * DD + c * 8);
    }

    const float beta = g_beta;
    const float thr_t = 60.f / beta + 2.0f;   // bf16+f32acc margin (proven)
    const float thr_s = 60.f / beta + 5.0f;   // f16 HFMA2 margin (proven R12)

    // B loader: 2 threads/row, 4 x 16B; SIMT region rows get chunk swizzle.
    const int pr = t >> 1;
    const int pc = (t & 1) * 4;
    const int psw = (pr >= TNT) ? ((pr >> 3) & 7) : 0;
    auto issue_b = [&](int buf, int bn) {
        const uint16_t* src = g_e16 + (size_t)(bn + pr) * DD;
        uint32_t drow = sbU[buf] + (uint32_t)pr * ROWB;
        #pragma unroll
        for (int c = 0; c < 4; c++) {
            int ch = pc + c;
            cp_async16(drow + (ch ^ psw) * 16, src + ch * 8);
        }
    };

    issue_b(0, blockIdx.x * TN);
    cp_commit();

    // ---- MMA role constants (warps 0..5; 2M x 3N grid; warp tile 64x32) ----
    const int warpM = wid / 3, warpN = wid % 3;       // valid for wid<6
    const int rowA = (lane & 7) + ((lane >> 3) & 1) * 8;
    const int kA   = ((lane >> 4) & 1) * 8;
    const int l16  = lane & 15;
    const int rowBf = l16 & 7;
    const int kB    = ((l16 >> 3) & 1) * 8;
    uint32_t aAddr[4], bOff[4];
    float x2a[4], x2b[4];
    float xminT = 0.f;
    if (wid < 6) {
        #pragma unroll
        for (int mi = 0; mi < 4; mi++)
            aAddr[mi] = sAbf + (uint32_t)(warpM * 64 + mi * 16 + rowA) * ROWB + kA * 2;
        #pragma unroll
        for (int ni = 0; ni < 4; ni++)
            bOff[ni] = (uint32_t)(warpN * 32 + ni * 8 + rowBf) * ROWB + kB * 2;
        #pragma unroll
        for (int mi = 0; mi < 4; mi++) {
            int r0 = bm + warpM * 64 + mi * 16 + (lane >> 2);
            x2a[mi] = g_x2[r0];
            x2b[mi] = g_x2[r0 + 8];
        }
        xminT = fminf(fminf(fminf(x2a[0], x2b[0]), fminf(x2a[1], x2b[1])),
                      fminf(fminf(x2a[2], x2b[2]), fminf(x2a[3], x2b[3])));
    }

    // ---- SIMT role constants (warps 6,7; 64 rows x 32 cols; thread 8x8) ----
    const int sw  = wid - 6;          // 0,1
    const int rg  = lane >> 2;        // 0..7 (row groups of 8)
    const int cgp = lane & 3;         // 0..3 (col groups of 8)
    float sx2[8];
    float sxmin = 0.f;
    uint32_t aAddrS = 0, aSwiz = 0, bSwiz = 0;
    if (wid >= 6) {
        #pragma unroll
        for (int q = 0; q < 2; q++) {
            float4 f = *(const float4*)&g_x2[bm + sw * 64 + rg * 8 + q * 4];
            sx2[4*q+0] = f.x; sx2[4*q+1] = f.y; sx2[4*q+2] = f.z; sx2[4*q+3] = f.w;
        }
        sxmin = sx2[0];
        #pragma unroll
        for (int i = 1; i < 8; i++) sxmin = fminf(sxmin, sx2[i]);
        aAddrS = sAf + (uint32_t)(sw * 64 + rg * 8) * ROWB;
        aSwiz = rg;                       // (row>>3)&7 for this thread's rows
        bSwiz = (12 + cgp) & 7;           // ((96 + cgp*8 + cc)>>3)&7
    }

    int it = 0;
    for (int et = blockIdx.x; et < NT; et += GCOLS, it++) {
        const int bn = et * TN;
        const int buf = it & 1;
        const uint32_t cur = sbU[buf];
        const int etn = et + GCOLS;
        if (etn < NT) {
            issue_b(buf ^ 1, etn * TN);
            cp_commit();
            cp_wait<1>();
        } else {
            cp_wait<0>();
        }
        __syncthreads();

        if (wid < 6) {
            // ================= MMA slice: cols bn .. bn+95 =================
            float2 e2p[4];
            #pragma unroll
            for (int ni = 0; ni < 4; ni++)
                e2p[ni] = *(const float2*)&g_e2[bn + warpN * 32 + ni * 8 +
                                                2 * (lane & 3)];
            float acc[4][4][4];
            #pragma unroll
            for (int mi = 0; mi < 4; mi++)
                #pragma unroll
                for (int ni = 0; ni < 4; ni++)
                    #pragma unroll
                    for (int r = 0; r < 4; r++) acc[mi][ni][r] = 0.f;
            #pragma unroll
            for (int ks = 0; ks < 4; ks++) {
                const int k0b = ks * 32;
                uint32_t af[4][4];
                #pragma unroll
                for (int mi = 0; mi < 4; mi++) ldsm_x4(af[mi], aAddr[mi] + k0b);
                uint32_t bf[4][2];
                #pragma unroll
                for (int ni = 0; ni < 4; ni++) ldsm_x2(bf[ni], cur + bOff[ni] + k0b);
                #pragma unroll
                for (int mi = 0; mi < 4; mi++)
                    #pragma unroll
                    for (int ni = 0; ni < 4; ni++)
                        mma_bf16(acc[mi][ni], af[mi], bf[ni]);
            }
            // hierarchical gate per ni
            #pragma unroll
            for (int ni = 0; ni < 4; ni++) {
                float mx = acc[0][ni][0];
                #pragma unroll
                for (int mi = 0; mi < 4; mi++)
                    #pragma unroll
                    for (int r = 0; r < 4; r++) mx = fmaxf(mx, acc[mi][ni][r]);
                float e2mn = fminf(e2p[ni].x, e2p[ni].y);
                if (xminT + e2mn - 2.f * mx < thr_t) {
                    #pragma unroll
                    for (int mi = 0; mi < 4; mi++)
                        #pragma unroll
                        for (int r = 0; r < 4; r++) {
                            float xv = (r >= 2) ? x2b[mi] : x2a[mi];
                            float ev = (r & 1) ? e2p[ni].y : e2p[ni].x;
                            if (xv + ev - 2.f * acc[mi][ni][r] < thr_t) {
                                int row = bm + warpM * 64 + mi * 16 +
                                          (lane >> 2) + ((r >> 1) << 3);
                                int col = bn + warpN * 32 + ni * 8 +
                                          2 * (lane & 3) + (r & 1);
                                push_surv(row, col);
                            }
                        }
                }
            }
        } else {
            // ================ SIMT slice: cols bn+96 .. bn+127 ================
            float e2c[8];
            #pragma unroll
            for (int q = 0; q < 2; q++) {
                float4 f = *(const float4*)&g_e2[bn + TNT + cgp * 8 + q * 4];
                e2c[4*q+0] = f.x; e2c[4*q+1] = f.y;
                e2c[4*q+2] = f.z; e2c[4*q+3] = f.w;
            }
            float e2mn = e2c[0];
            #pragma unroll
            for (int i = 1; i < 8; i++) e2mn = fminf(e2mn, e2c[i]);

            __half2 acc[8][8];
            #pragma unroll
            for (int r = 0; r < 8; r++)
                #pragma unroll
                for (int c = 0; c < 8; c++)
                    acc[r][c] = __half2half2(__ushort_as_half(0));

            const uint32_t bBase = cur + (uint32_t)(TNT + cgp * 8) * ROWB;
            #pragma unroll
            for (int kb2 = 0; kb2 < 16; kb2++) {
                const int ch = kb2 >> 1, h8 = (kb2 & 1) * 8;
                const uint32_t aoff = (uint32_t)((ch ^ aSwiz) * 16 + h8);
                const uint32_t boff = (uint32_t)((ch ^ bSwiz) * 16 + h8);
                uint32_t ra[8][2], rb[8][2];
                #pragma unroll
                for (int rr = 0; rr < 8; rr++)
                    lds64(ra[rr], aAddrS + (uint32_t)rr * ROWB + aoff);
                #pragma unroll
                for (int cc = 0; cc < 8; cc++)
                    lds64(rb[cc], bBase + (uint32_t)cc * ROWB + boff);
                #pragma unroll
                for (int j = 0; j < 2; j++)
                    #pragma unroll
                    for (int r = 0; r < 8; r++)
                        #pragma unroll
                        for (int c = 0; c < 8; c++)
                            acc[r][c] = __hfma2(*(__half2*)&ra[r][j],
                                                *(__half2*)&rb[c][j], acc[r][c]);
            }

            // gate: componentwise hmax2 tree -> upper bound on max dot
            __half2 mm = acc[0][0];
            #pragma unroll
            for (int r = 0; r < 8; r++)
                #pragma unroll
                for (int c = 0; c < 8; c++) mm = __hmax2(mm, acc[r][c]);
            float dmax = __low2float(mm) + __high2float(mm);
            if (sxmin + e2mn - 2.f * dmax < thr_s) {
                #pragma unroll
                for (int r = 0; r < 8; r++)
                    #pragma unroll
                    for (int c = 0; c < 8; c++) {
                        float dot = __low2float(acc[r][c]) +
                                    __high2float(acc[r][c]);
                        if (sx2[r] + e2c[c] - 2.f * dot < thr_s) {
                            int row = bm + sw * 64 + rg * 8 + r;
                            int col = bn + TNT + cgp * 8 + c;
                            push_surv(row, col);
                        }
                    }
            }
        }
        __syncthreads();
    }
}

// ---------------------------------------------------------------------------
// Survivors: exact fp32 recompute + exp + scatter-add; last block finalizes.
// ---------------------------------------------------------------------------
__global__ void survivor_finalize_kernel(const float* __restrict__ x,
                                         const float* __restrict__ ex,
                                         const int* __restrict__ labels,
                                         float* __restrict__ out,
                                         int B, int NE, int nout) {
    unsigned n = g_nsurv;
    if (n > MAXSURV) n = MAXSURV;
    const float beta = g_beta;
    for (unsigned i = blockIdx.x * blockDim.x + threadIdx.x; i < n;
         i += gridDim.x * blockDim.x) {
        unsigned p = g_surv[i];
        int row = (int)(p >> 16);
        int col = (int)(p & 0xFFFFu);
        if (row >= B || col >= NE) continue;
        const float* xr = x  + (size_t)row * DD;
        const float* er = ex + (size_t)col * DD;
        float s = 0.f;
        #pragma unroll
        for (int q = 0; q < DD / 4; q++) {
            float4 a = ((const float4*)xr)[q];
            float4 e = ((const float4*)er)[q];
            s += a.x*e.x + a.y*e.y + a.z*e.z + a.w*e.w;
        }
        float d2 = fmaxf(g_x2[row] + g_e2[col] - 2.f * s, 0.f);
        float bd = beta * d2;
        // skipped mass <= NE*exp(-60) << 1e-3 * EPS
        if (bd < 60.f)
            atomicAdd(&g_class[row * NUM_CLASSES + labels[col]], expf(-bd));
    }

    __shared__ unsigned s_last;
    __threadfence();
    __syncthreads();
    if (threadIdx.x == 0)
        s_last = (atomicAdd(&g_done, 1u) == gridDim.x - 1) ? 1u : 0u;
    __syncthreads();
    if (s_last) {
        __threadfence();
        for (int i = threadIdx.x; i < nout; i += blockDim.x)
            out[i] = GAMMA * logf(g_class[i] + EPS);
    }
}

// ---------------------------------------------------------------------------
extern "C" void kernel_launch(void* const* d_in, const int* in_sizes, int n_in,
                              void* d_out, int out_size) {
    const float* x        = (const float*)d_in[0];
    const float* ex       = (const float*)d_in[1];
    const int*   labels   = (const int*)d_in[2];
    const float* beta_raw = (const float*)d_in[3];
    float* out = (float*)d_out;

    const int B  = in_sizes[0] / DD;
    const int NE = in_sizes[1] / DD;

    const int prep_blocks = (NE_PAD + MAXB) / 64;   // 798
    prep_kernel<<<prep_blocks, 256>>>(x, ex, beta_raw, B, NE);

    static int smem_set = 0;
    if (!smem_set) {
        cudaFuncSetAttribute(exemplar_hybrid_kernel,
                             cudaFuncAttributeMaxDynamicSharedMemorySize, SM_TOT);
        smem_set = 1;
    }
    dim3 grid(GCOLS, (B + TM - 1) / TM);            // 37 x 8 = 296
    exemplar_hybrid_kernel<<<grid, 256, SM_TOT>>>(B, NE);

    survivor_finalize_kernel<<<148, 256>>>(x, ex, labels, out, B, NE, out_size);
}

// round 16
// speedup vs baseline: 2.0852x; 2.0852x over previous
#include <cuda_runtime.h>
#include <cuda_bf16.h>
#include <stdint.h>
#include <math.h>

// ---------------------------------------------------------------------------
// Problem constants
// ---------------------------------------------------------------------------
#define NUM_CLASSES 10
#define DD     64
#define MAXB   1024
#define NE_PAD 50048           // 391 tiles of 128
#define GAMMA  1.0f
#define EPS    1e-12f

// Tiling (R8-proven skeleton): bf16 HMMA f32-acc, 128x128 tile, 8 warps.
#define TM 128
#define TN 128
#define GCOLS 37               // grid = 8 x 37 = 296 CTAs = 2/SM, one wave
#define ROWB 144               // smem row stride (64 bf16 + 8 pad)

#define SM_A   0
#define SM_B0  (TM * ROWB)             // 18432
#define SM_B1  (SM_B0 + TN * ROWB)     // 36864
#define SM_TOT (SM_B1 + TN * ROWB)     // 55296 (dynamic smem)

#define MAXSURV (1u * 1024u * 1024u)

// ---------------------------------------------------------------------------
// Scratch (__device__ globals; no cudaMalloc allowed)
// ---------------------------------------------------------------------------
__device__ __nv_bfloat16 g_eh[(size_t)NE_PAD * DD];
__device__ __nv_bfloat16 g_xh[(size_t)MAXB * DD];
__device__ float g_e2[NE_PAD];
__device__ float g_x2[MAXB];
__device__ float g_class[MAXB * NUM_CLASSES];
__device__ float g_beta;
__device__ unsigned g_nsurv, g_done;
__device__ unsigned g_surv[MAXSURV];

// ---------------------------------------------------------------------------
// PTX helpers (baseline ISA only: ldmatrix, mma.sync, cp.async)
// ---------------------------------------------------------------------------
__device__ __forceinline__ uint32_t smem_to_u32(const void* p) {
    uint32_t a;
    asm("{ .reg .u64 t; cvta.to.shared.u64 t, %1; cvt.u32.u64 %0, t; }"
        : "=r"(a) : "l"(p));
    return a;
}
__device__ __forceinline__ void ldsm_x4(uint32_t* r, uint32_t addr) {
    asm volatile("ldmatrix.sync.aligned.m8n8.x4.shared.b16 {%0,%1,%2,%3}, [%4];"
                 : "=r"(r[0]), "=r"(r[1]), "=r"(r[2]), "=r"(r[3]) : "r"(addr));
}
__device__ __forceinline__ void ldsm_x2(uint32_t* r, uint32_t addr) {
    asm volatile("ldmatrix.sync.aligned.m8n8.x2.shared.b16 {%0,%1}, [%2];"
                 : "=r"(r[0]), "=r"(r[1]) : "r"(addr));
}
__device__ __forceinline__ void mma_bf16(float* c, const uint32_t* a,
                                         const uint32_t* b) {
    asm volatile(
        "mma.sync.aligned.m16n8k16.row.col.f32.bf16.bf16.f32 "
        "{%0,%1,%2,%3}, {%4,%5,%6,%7}, {%8,%9}, {%0,%1,%2,%3};"
        : "+f"(c[0]), "+f"(c[1]), "+f"(c[2]), "+f"(c[3])
        : "r"(a[0]), "r"(a[1]), "r"(a[2]), "r"(a[3]), "r"(b[0]), "r"(b[1]));
}
__device__ __forceinline__ void cp_async16(uint32_t dst, const void* src) {
    asm volatile("cp.async.cg.shared.global [%0], [%1], 16;"
                 :: "r"(dst), "l"(src) : "memory");
}
__device__ __forceinline__ void cp_commit() {
    asm volatile("cp.async.commit_group;" ::: "memory");
}
template <int N>
__device__ __forceinline__ void cp_wait() {
    asm volatile("cp.async.wait_group %0;" :: "n"(N) : "memory");
}

// ---------------------------------------------------------------------------
// Prep: bf16 conversion (padded), exact L2 norms, beta, zero bins.
// (Unchanged from R8 — measured 6.75-7.1 us.)
// ---------------------------------------------------------------------------
__global__ void prep_kernel(const float* __restrict__ x,
                            const float* __restrict__ ex,
                            const float* __restrict__ beta_raw,
                            int B, int NE) {
    const int t = threadIdx.x;
    const int gid = blockIdx.x * 256 + t;
    if (gid < MAXB * NUM_CLASSES) g_class[gid] = 0.f;
    if (gid == 0) {
        float br = beta_raw[0];
        g_beta = (br > 20.f) ? br : log1pf(expf(br));
        g_nsurv = 0u;
        g_done  = 0u;
    }
    const int R = blockIdx.x * 32 + (t >> 3);   // padded row index
    const int part = t & 7;                      // 8-float segment
    bool is_x = false;
    int outr = R;
    const float* src = nullptr;
    if (R < NE_PAD) {
        if (R < NE) src = ex + (size_t)R * DD + part * 8;
    } else {
        int xr = R - NE_PAD;
        if (xr >= MAXB) return;
        is_x = true; outr = xr;
        if (xr < B) src = x + (size_t)xr * DD + part * 8;
    }
    float v[8];
    float s = 0.f;
    if (src) {
        #pragma unroll
        for (int q = 0; q < 2; q++) {
            float4 f = ((const float4*)src)[q];
            v[4*q+0] = f.x; v[4*q+1] = f.y; v[4*q+2] = f.z; v[4*q+3] = f.w;
            s += f.x*f.x + f.y*f.y + f.z*f.z + f.w*f.w;
        }
    } else {
        #pragma unroll
        for (int q = 0; q < 8; q++) v[q] = 0.f;
    }
    #pragma unroll
    for (int d = 1; d <= 4; d <<= 1)
        s += __shfl_xor_sync(0xFFFFFFFFu, s, d);
    alignas(16) __nv_bfloat16 hb[8];
    #pragma unroll
    for (int q = 0; q < 8; q++) hb[q] = __float2bfloat16(v[q]);
    __nv_bfloat16* dst = (is_x ? (g_xh + (size_t)outr * DD)
                               : (g_eh + (size_t)outr * DD)) + part * 8;
    *(uint4*)dst = *(uint4*)hb;
    if (part == 0) {
        if (is_x) g_x2[outr] = (outr < B) ? s : 0.f;
        else      g_e2[outr] = (outr < NE) ? s : 3.0e8f;  // padding never fires
    }
}

// ---------------------------------------------------------------------------
// Main: bf16 HMMA filter GEMM (R8 skeleton). ONLY change vs R8: the epilogue
// is a hierarchical fmax-tree gate (15 FMNMX + 1 compare per ni) with a rare
// per-element scan, instead of 320 per-element instructions.
// Conservative: min over group of (x2+e2-2*acc) >= xmin + e2min - 2*max(acc),
// so no true survivor can be missed. Margin 2 >> bf16 dot error (~0.35).
// ---------------------------------------------------------------------------
__global__ void __launch_bounds__(256, 2)
exemplar_mma_kernel(int B, int NE) {
    extern __shared__ char smem[];
    const uint32_t saU = smem_to_u32(smem) + SM_A;
    const uint32_t sb0 = smem_to_u32(smem) + SM_B0;
    const uint32_t sb1 = smem_to_u32(smem) + SM_B1;

    const int t = threadIdx.x;
    const int wid = t >> 5, lane = t & 31;
    const int warpM = wid >> 2;            // 0..1
    const int warpN = wid & 3;             // 0..3
    const int bm = blockIdx.y * TM;
    const int NT = (NE + TN - 1) / TN;

    // Load A tile (128 rows x 64 bf16) once.
    for (int i = t; i < TM * 8; i += 256) {
        int r = i >> 3, c = i & 7;
        *(uint4*)(smem + SM_A + r * ROWB + c * 16) =
            *(const uint4*)(g_xh + (size_t)(bm + r) * DD + c * 8);
    }

    // ldmatrix lane-address components
    const int rowA = (lane & 7) + ((lane >> 3) & 1) * 8;
    const int kA   = ((lane >> 4) & 1) * 8;
    const int l16  = lane & 15;
    const int rowBf = l16 & 7;
    const int kB    = ((l16 >> 3) & 1) * 8;

    uint32_t aAddr[4];
    #pragma unroll
    for (int mi = 0; mi < 4; mi++)
        aAddr[mi] = saU + (uint32_t)(warpM * 64 + mi * 16 + rowA) * ROWB + kA * 2;
    uint32_t bOff[4];
    #pragma unroll
    for (int ni = 0; ni < 4; ni++)
        bOff[ni] = (uint32_t)(warpN * 32 + ni * 8 + rowBf) * ROWB + kB * 2;

    const float beta = g_beta;
    const float thr  = 60.f / beta + 2.f;   // margin 2 >> bf16 dot err (~0.35)

    float x2a[4], x2b[4];
    #pragma unroll
    for (int mi = 0; mi < 4; mi++) {
        int r0 = bm + warpM * 64 + mi * 16 + (lane >> 2);
        x2a[mi] = g_x2[r0];
        x2b[mi] = g_x2[r0 + 8];
    }
    const float xmin = fminf(fminf(fminf(x2a[0], x2b[0]), fminf(x2a[1], x2b[1])),
                             fminf(fminf(x2a[2], x2b[2]), fminf(x2a[3], x2b[3])));

    // cp.async B-tile issue: 4 x 16B per thread.
    const int pr = t >> 1;
    const int pc = (t & 1) * 2;
    auto issue_b = [&](uint32_t sbase, int bn) {
        const __nv_bfloat16* src = g_eh + (size_t)(bn + pr) * DD;
        uint32_t drow = sbase + (uint32_t)pr * ROWB;
        cp_async16(drow + (pc + 0) * 16, src + (pc + 0) * 8);
        cp_async16(drow + (pc + 1) * 16, src + (pc + 1) * 8);
        cp_async16(drow + (pc + 4) * 16, src + (pc + 4) * 8);
        cp_async16(drow + (pc + 5) * 16, src + (pc + 5) * 8);
    };

    issue_b(sb0, blockIdx.x * TN);
    cp_commit();

    int it = 0;
    for (int et = blockIdx.x; et < NT; et += GCOLS, it++) {
        const int bn = et * TN;
        const uint32_t cur = (it & 1) ? sb1 : sb0;
        const uint32_t nxt = (it & 1) ? sb0 : sb1;
        const int etn = et + GCOLS;
        if (etn < NT) {
            issue_b(nxt, etn * TN);
            cp_commit();
            cp_wait<1>();
        } else {
            cp_wait<0>();
        }
        __syncthreads();

        float2 e2p[4];
        #pragma unroll
        for (int ni = 0; ni < 4; ni++)
            e2p[ni] = *(const float2*)&g_e2[bn + warpN * 32 + ni * 8 + 2 * (lane & 3)];

        float acc[4][4][4];
        #pragma unroll
        for (int mi = 0; mi < 4; mi++)
            #pragma unroll
            for (int ni = 0; ni < 4; ni++)
                #pragma unroll
                for (int r = 0; r < 4; r++) acc[mi][ni][r] = 0.f;

        #pragma unroll
        for (int ks = 0; ks < 4; ks++) {
            const int k0b = ks * 32;
            uint32_t af[4][4];
            #pragma unroll
            for (int mi = 0; mi < 4; mi++) ldsm_x4(af[mi], aAddr[mi] + k0b);
            uint32_t bf[4][2];
            #pragma unroll
            for (int ni = 0; ni < 4; ni++) ldsm_x2(bf[ni], cur + bOff[ni] + k0b);
            #pragma unroll
            for (int mi = 0; mi < 4; mi++)
                #pragma unroll
                for (int ni = 0; ni < 4; ni++)
                    mma_bf16(acc[mi][ni], af[mi], bf[ni]);
        }

        // ---- Hierarchical gate (the one change vs R8) ----
        #pragma unroll
        for (int ni = 0; ni < 4; ni++) {
            float mx = acc[0][ni][0];
            #pragma unroll
            for (int mi = 0; mi < 4; mi++)
                #pragma unroll
                for (int r = 0; r < 4; r++) mx = fmaxf(mx, acc[mi][ni][r]);
            float e2mn = fminf(e2p[ni].x, e2p[ni].y);
            if (xmin + e2mn - 2.f * mx < thr) {
                // rare detailed scan of this column group's 16 elements
                #pragma unroll
                for (int mi = 0; mi < 4; mi++)
                    #pragma unroll
                    for (int r = 0; r < 4; r++) {
                        float x2v = (r >= 2) ? x2b[mi] : x2a[mi];
                        float e2v = (r & 1) ? e2p[ni].y : e2p[ni].x;
                        if (x2v + e2v - 2.f * acc[mi][ni][r] < thr) {
                            int row = bm + warpM * 64 + mi * 16 +
                                      (lane >> 2) + ((r >> 1) << 3);
                            int col = bn + warpN * 32 + ni * 8 +
                                      2 * (lane & 3) + (r & 1);
                            unsigned q = atomicAdd(&g_nsurv, 1u);
                            if (q < MAXSURV)
                                g_surv[q] = ((unsigned)row << 16) | (unsigned)col;
                        }
                    }
            }
        }
        __syncthreads();   // all reads of cur done before it is re-prefetched
    }
}

// ---------------------------------------------------------------------------
// Survivors: exact fp32 recompute + exp + scatter-add; last block finalizes
// logits = GAMMA * log(class_sims + EPS).
// ---------------------------------------------------------------------------
__global__ void survivor_finalize_kernel(const float* __restrict__ x,
                                         const float* __restrict__ ex,
                                         const int* __restrict__ labels,
                                         float* __restrict__ out,
                                         int B, int NE, int nout) {
    unsigned n = g_nsurv;
    if (n > MAXSURV) n = MAXSURV;
    const float beta = g_beta;
    for (unsigned i = blockIdx.x * blockDim.x + threadIdx.x; i < n;
         i += gridDim.x * blockDim.x) {
        unsigned p = g_surv[i];
        int row = (int)(p >> 16);
        int col = (int)(p & 0xFFFFu);
        if (row >= B || col >= NE) continue;
        const float* xr = x  + (size_t)row * DD;
        const float* er = ex + (size_t)col * DD;
        float s = 0.f;
        #pragma unroll
        for (int q = 0; q < DD / 4; q++) {
            float4 a = ((const float4*)xr)[q];
            float4 e = ((const float4*)er)[q];
            s += a.x*e.x + a.y*e.y + a.z*e.z + a.w*e.w;
        }
        float d2 = fmaxf(g_x2[row] + g_e2[col] - 2.f * s, 0.f);
        float bd = beta * d2;
        // skipped mass <= NE*exp(-60) << 1e-3 * EPS
        if (bd < 60.f)
            atomicAdd(&g_class[row * NUM_CLASSES + labels[col]], expf(-bd));
    }

    __shared__ unsigned s_last;
    __threadfence();
    __syncthreads();
    if (threadIdx.x == 0)
        s_last = (atomicAdd(&g_done, 1u) == gridDim.x - 1) ? 1u : 0u;
    __syncthreads();
    if (s_last) {
        __threadfence();
        for (int i = threadIdx.x; i < nout; i += blockDim.x)
            out[i] = GAMMA * logf(g_class[i] + EPS);
    }
}

// ---------------------------------------------------------------------------
extern "C" void kernel_launch(void* const* d_in, const int* in_sizes, int n_in,
                              void* d_out, int out_size) {
    const float* x        = (const float*)d_in[0];
    const float* ex       = (const float*)d_in[1];
    const int*   labels   = (const int*)d_in[2];
    const float* beta_raw = (const float*)d_in[3];
    float* out = (float*)d_out;

    const int B  = in_sizes[0] / DD;
    const int NE = in_sizes[1] / DD;

    const int prep_blocks = (NE_PAD + MAXB) / 32;   // 1596
    prep_kernel<<<prep_blocks, 256>>>(x, ex, beta_raw, B, NE);

    static int smem_set = 0;
    if (!smem_set) {
        cudaFuncSetAttribute(exemplar_mma_kernel,
                             cudaFuncAttributeMaxDynamicSharedMemorySize, SM_TOT);
        smem_set = 1;
    }
    dim3 grid(GCOLS, (B + TM - 1) / TM);            // 37 x 8
    exemplar_mma_kernel<<<grid, 256, SM_TOT>>>(B, NE);

    survivor_finalize_kernel<<<148, 256>>>(x, ex, labels, out, B, NE, out_size);
}

// round 17
// speedup vs baseline: 2.5580x; 1.2268x over previous
#include <cuda_runtime.h>
#include <cuda_bf16.h>
#include <stdint.h>
#include <math.h>

// ---------------------------------------------------------------------------
// Problem constants
// ---------------------------------------------------------------------------
#define NUM_CLASSES 10
#define DD     64
#define MAXB   1024
#define NE_PAD 50048           // 391 tiles of 128
#define GAMMA  1.0f
#define EPS    1e-12f

// Tiling (R8-proven skeleton): bf16 HMMA f32-acc, 128x128 tile, 8 warps.
// CHANGE vs R8: 4-stage cp.async ring, ONE barrier per tile (was 2).
#define TM 128
#define TN 128
#define GCOLS 37               // grid = 8 x 37 = 296 CTAs = 2/SM, one wave
#define ROWB 144               // smem row stride (64 bf16 + 8 pad)
#define NSTAGE 4

#define SM_A   0
#define SM_B   (TM * ROWB)             // 18432; 4 stage buffers follow
#define SM_TOT (SM_B + NSTAGE * TN * ROWB)   // 92160 (dynamic smem)

#define MAXSURV (1u * 1024u * 1024u)

// ---------------------------------------------------------------------------
// Scratch (__device__ globals; no cudaMalloc allowed)
// ---------------------------------------------------------------------------
__device__ __nv_bfloat16 g_eh[(size_t)NE_PAD * DD];
__device__ __nv_bfloat16 g_xh[(size_t)MAXB * DD];
__device__ float g_e2[NE_PAD];
__device__ float g_x2[MAXB];
__device__ float g_class[MAXB * NUM_CLASSES];
__device__ float g_beta;
__device__ unsigned g_nsurv, g_done;
__device__ unsigned g_surv[MAXSURV];

// ---------------------------------------------------------------------------
// PTX helpers (baseline ISA only: ldmatrix, mma.sync, cp.async)
// ---------------------------------------------------------------------------
__device__ __forceinline__ uint32_t smem_to_u32(const void* p) {
    uint32_t a;
    asm("{ .reg .u64 t; cvta.to.shared.u64 t, %1; cvt.u32.u64 %0, t; }"
        : "=r"(a) : "l"(p));
    return a;
}
__device__ __forceinline__ void ldsm_x4(uint32_t* r, uint32_t addr) {
    asm volatile("ldmatrix.sync.aligned.m8n8.x4.shared.b16 {%0,%1,%2,%3}, [%4];"
                 : "=r"(r[0]), "=r"(r[1]), "=r"(r[2]), "=r"(r[3]) : "r"(addr));
}
__device__ __forceinline__ void ldsm_x2(uint32_t* r, uint32_t addr) {
    asm volatile("ldmatrix.sync.aligned.m8n8.x2.shared.b16 {%0,%1}, [%2];"
                 : "=r"(r[0]), "=r"(r[1]) : "r"(addr));
}
__device__ __forceinline__ void mma_bf16(float* c, const uint32_t* a,
                                         const uint32_t* b) {
    asm volatile(
        "mma.sync.aligned.m16n8k16.row.col.f32.bf16.bf16.f32 "
        "{%0,%1,%2,%3}, {%4,%5,%6,%7}, {%8,%9}, {%0,%1,%2,%3};"
        : "+f"(c[0]), "+f"(c[1]), "+f"(c[2]), "+f"(c[3])
        : "r"(a[0]), "r"(a[1]), "r"(a[2]), "r"(a[3]), "r"(b[0]), "r"(b[1]));
}
__device__ __forceinline__ void cp_async16(uint32_t dst, const void* src) {
    asm volatile("cp.async.cg.shared.global [%0], [%1], 16;"
                 :: "r"(dst), "l"(src) : "memory");
}
__device__ __forceinline__ void cp_commit() {
    asm volatile("cp.async.commit_group;" ::: "memory");
}
template <int N>
__device__ __forceinline__ void cp_wait() {
    asm volatile("cp.async.wait_group %0;" :: "n"(N) : "memory");
}

// ---------------------------------------------------------------------------
// Prep: bf16 conversion (padded), exact L2 norms, beta, zero bins.
// (R8 verbatim — measured 6.5-7.1 us.)
// ---------------------------------------------------------------------------
__global__ void prep_kernel(const float* __restrict__ x,
                            const float* __restrict__ ex,
                            const float* __restrict__ beta_raw,
                            int B, int NE) {
    const int t = threadIdx.x;
    const int gid = blockIdx.x * 256 + t;
    if (gid < MAXB * NUM_CLASSES) g_class[gid] = 0.f;
    if (gid == 0) {
        float br = beta_raw[0];
        g_beta = (br > 20.f) ? br : log1pf(expf(br));
        g_nsurv = 0u;
        g_done  = 0u;
    }
    const int R = blockIdx.x * 32 + (t >> 3);   // padded row index
    const int part = t & 7;                      // 8-float segment
    bool is_x = false;
    int outr = R;
    const float* src = nullptr;
    if (R < NE_PAD) {
        if (R < NE) src = ex + (size_t)R * DD + part * 8;
    } else {
        int xr = R - NE_PAD;
        if (xr >= MAXB) return;
        is_x = true; outr = xr;
        if (xr < B) src = x + (size_t)xr * DD + part * 8;
    }
    float v[8];
    float s = 0.f;
    if (src) {
        #pragma unroll
        for (int q = 0; q < 2; q++) {
            float4 f = ((const float4*)src)[q];
            v[4*q+0] = f.x; v[4*q+1] = f.y; v[4*q+2] = f.z; v[4*q+3] = f.w;
            s += f.x*f.x + f.y*f.y + f.z*f.z + f.w*f.w;
        }
    } else {
        #pragma unroll
        for (int q = 0; q < 8; q++) v[q] = 0.f;
    }
    #pragma unroll
    for (int d = 1; d <= 4; d <<= 1)
        s += __shfl_xor_sync(0xFFFFFFFFu, s, d);
    alignas(16) __nv_bfloat16 hb[8];
    #pragma unroll
    for (int q = 0; q < 8; q++) hb[q] = __float2bfloat16(v[q]);
    __nv_bfloat16* dst = (is_x ? (g_xh + (size_t)outr * DD)
                               : (g_eh + (size_t)outr * DD)) + part * 8;
    *(uint4*)dst = *(uint4*)hb;
    if (part == 0) {
        if (is_x) g_x2[outr] = (outr < B) ? s : 0.f;
        else      g_e2[outr] = (outr < NE) ? s : 3.0e8f;  // padding never fires
    }
}

// ---------------------------------------------------------------------------
// Main: bf16 HMMA filter GEMM (R8 skeleton + 4-stage / 1-barrier pipeline).
// Epilogue: R8's proven per-element branchless mask (thr pre-folded into e2).
// ---------------------------------------------------------------------------
__global__ void __launch_bounds__(256, 2)
exemplar_mma_kernel(int B, int NE) {
    extern __shared__ char smem[];
    const uint32_t saU = smem_to_u32(smem) + SM_A;
    uint32_t sbU[NSTAGE];
    #pragma unroll
    for (int j = 0; j < NSTAGE; j++)
        sbU[j] = smem_to_u32(smem) + SM_B + j * (TN * ROWB);

    const int t = threadIdx.x;
    const int wid = t >> 5, lane = t & 31;
    const int warpM = wid >> 2;            // 0..1
    const int warpN = wid & 3;             // 0..3
    const int bm = blockIdx.y * TM;
    const int NT = (NE + TN - 1) / TN;

    // Load A tile (128 rows x 64 bf16) once.
    for (int i = t; i < TM * 8; i += 256) {
        int r = i >> 3, c = i & 7;
        *(uint4*)(smem + SM_A + r * ROWB + c * 16) =
            *(const uint4*)(g_xh + (size_t)(bm + r) * DD + c * 8);
    }

    // ldmatrix lane-address components
    const int rowA = (lane & 7) + ((lane >> 3) & 1) * 8;
    const int kA   = ((lane >> 4) & 1) * 8;
    const int l16  = lane & 15;
    const int rowBf = l16 & 7;
    const int kB    = ((l16 >> 3) & 1) * 8;

    uint32_t aAddr[4];
    #pragma unroll
    for (int mi = 0; mi < 4; mi++)
        aAddr[mi] = saU + (uint32_t)(warpM * 64 + mi * 16 + rowA) * ROWB + kA * 2;
    uint32_t bOff[4];
    #pragma unroll
    for (int ni = 0; ni < 4; ni++)
        bOff[ni] = (uint32_t)(warpN * 32 + ni * 8 + rowBf) * ROWB + kB * 2;

    const float beta = g_beta;
    const float thr  = 60.f / beta + 2.f;   // margin 2 >> bf16 dot err (~0.35)

    float x2a[4], x2b[4];
    #pragma unroll
    for (int mi = 0; mi < 4; mi++) {
        int r0 = bm + warpM * 64 + mi * 16 + (lane >> 2);
        x2a[mi] = g_x2[r0];
        x2b[mi] = g_x2[r0 + 8];
    }

    // cp.async B-tile issue: 4 x 16B per thread.
    const int pr = t >> 1;
    const int pc = (t & 1) * 2;
    auto issue_b = [&](uint32_t sbase, int bn) {
        const __nv_bfloat16* src = g_eh + (size_t)(bn + pr) * DD;
        uint32_t drow = sbase + (uint32_t)pr * ROWB;
        cp_async16(drow + (pc + 0) * 16, src + (pc + 0) * 8);
        cp_async16(drow + (pc + 1) * 16, src + (pc + 1) * 8);
        cp_async16(drow + (pc + 4) * 16, src + (pc + 4) * 8);
        cp_async16(drow + (pc + 5) * 16, src + (pc + 5) * 8);
    };

    // Prologue: prefetch tiles 0..2 (one commit group per tile; empty groups
    // are committed anyway to keep wait_group accounting uniform).
    #pragma unroll
    for (int j = 0; j < NSTAGE - 1; j++) {
        int et = blockIdx.x + j * GCOLS;
        if (et < NT) issue_b(sbU[j], et * TN);
        cp_commit();
    }

    int it = 0;
    for (int et = blockIdx.x; et < NT; et += GCOLS, it++) {
        const uint32_t cur = sbU[it & (NSTAGE - 1)];
        const int bn = et * TN;

        // Tile it's group complete (newest 2 pending = tiles it+1, it+2).
        cp_wait<NSTAGE - 2>();
        // ONE barrier: (a) makes all threads' cp.async data for tile it
        // visible, (b) guarantees everyone finished computing tile it-1, so
        // re-issuing into buffer (it+3)&3 == (it-1)&3 below is race-free.
        __syncthreads();

        const int etn = et + (NSTAGE - 1) * GCOLS;
        if (etn < NT) issue_b(sbU[(it + NSTAGE - 1) & (NSTAGE - 1)], etn * TN);
        cp_commit();

        // e2 for this thread's 8 cols, thr pre-folded.
        float2 e2p[4];
        #pragma unroll
        for (int ni = 0; ni < 4; ni++) {
            float2 e = *(const float2*)&g_e2[bn + warpN * 32 + ni * 8 +
                                             2 * (lane & 3)];
            e2p[ni].x = e.x - thr;
            e2p[ni].y = e.y - thr;
        }

        float acc[4][4][4];
        #pragma unroll
        for (int mi = 0; mi < 4; mi++)
            #pragma unroll
            for (int ni = 0; ni < 4; ni++)
                #pragma unroll
                for (int r = 0; r < 4; r++) acc[mi][ni][r] = 0.f;

        #pragma unroll
        for (int ks = 0; ks < 4; ks++) {
            const int k0b = ks * 32;
            uint32_t af[4][4];
            #pragma unroll
            for (int mi = 0; mi < 4; mi++) ldsm_x4(af[mi], aAddr[mi] + k0b);
            uint32_t bf[4][2];
            #pragma unroll
            for (int ni = 0; ni < 4; ni++) ldsm_x2(bf[ni], cur + bOff[ni] + k0b);
            #pragma unroll
            for (int mi = 0; mi < 4; mi++)
                #pragma unroll
                for (int ni = 0; ni < 4; ni++)
                    mma_bf16(acc[mi][ni], af[mi], bf[ni]);
        }

        // Branchless per-element gate -> 64-bit survivor mask (R8 form).
        uint32_t m0 = 0u, m1 = 0u;
        #pragma unroll
        for (int mi = 0; mi < 4; mi++) {
            #pragma unroll
            for (int ni = 0; ni < 4; ni++) {
                #pragma unroll
                for (int r = 0; r < 4; r++) {
                    float x2v = (r >= 2) ? x2b[mi] : x2a[mi];
                    float ev  = (r & 1) ? e2p[ni].y : e2p[ni].x;
                    // s < 0  <=>  x2 + e2 - 2*acc < thr
                    float s = fmaf(-2.f, acc[mi][ni][r], x2v) + ev;
                    uint32_t p = __float_as_uint(s) >> 31;
                    int idx = (mi * 4 + ni) * 4 + r;
                    if (idx < 32) m0 |= p << idx;
                    else          m1 |= p << (idx - 32);
                }
            }
        }

        // Very rare: push packed (row,col) survivors straight to global queue.
        if (m0 | m1) {
            int cnt = __popc(m0) + __popc(m1);
            unsigned base = atomicAdd(&g_nsurv, (unsigned)cnt);
            const int rbase = bm + warpM * 64 + (lane >> 2);
            const int cbase = bn + warpN * 32 + 2 * (lane & 3);
            #pragma unroll
            for (int half = 0; half < 2; half++) {
                uint32_t m = half ? m1 : m0;
                while (m) {
                    int i = __ffs(m) - 1;
                    m &= m - 1;
                    int r  = i & 3;
                    int ni = (i >> 2) & 3;
                    int mi = (i >> 4) + half * 2;
                    int row = rbase + mi * 16 + ((r >> 1) << 3);
                    int col = cbase + ni * 8 + (r & 1);
                    if (base < MAXSURV)
                        g_surv[base] = ((unsigned)row << 16) | (unsigned)col;
                    base++;
                }
            }
        }
        // no trailing barrier: next iteration's single barrier protects reuse
    }
}

// ---------------------------------------------------------------------------
// Survivors: exact fp32 recompute + exp + scatter-add; last block finalizes
// logits = GAMMA * log(class_sims + EPS).
// ---------------------------------------------------------------------------
__global__ void survivor_finalize_kernel(const float* __restrict__ x,
                                         const float* __restrict__ ex,
                                         const int* __restrict__ labels,
                                         float* __restrict__ out,
                                         int B, int NE, int nout) {
    unsigned n = g_nsurv;
    if (n > MAXSURV) n = MAXSURV;
    const float beta = g_beta;
    for (unsigned i = blockIdx.x * blockDim.x + threadIdx.x; i < n;
         i += gridDim.x * blockDim.x) {
        unsigned p = g_surv[i];
        int row = (int)(p >> 16);
        int col = (int)(p & 0xFFFFu);
        if (row >= B || col >= NE) continue;
        const float* xr = x  + (size_t)row * DD;
        const float* er = ex + (size_t)col * DD;
        float s = 0.f;
        #pragma unroll
        for (int q = 0; q < DD / 4; q++) {
            float4 a = ((const float4*)xr)[q];
            float4 e = ((const float4*)er)[q];
            s += a.x*e.x + a.y*e.y + a.z*e.z + a.w*e.w;
        }
        float d2 = fmaxf(g_x2[row] + g_e2[col] - 2.f * s, 0.f);
        float bd = beta * d2;
        // skipped mass <= NE*exp(-60) << 1e-3 * EPS
        if (bd < 60.f)
            atomicAdd(&g_class[row * NUM_CLASSES + labels[col]], expf(-bd));
    }

    __shared__ unsigned s_last;
    __threadfence();
    __syncthreads();
    if (threadIdx.x == 0)
        s_last = (atomicAdd(&g_done, 1u) == gridDim.x - 1) ? 1u : 0u;
    __syncthreads();
    if (s_last) {
        __threadfence();
        for (int i = threadIdx.x; i < nout; i += blockDim.x)
            out[i] = GAMMA * logf(g_class[i] + EPS);
    }
}

// ---------------------------------------------------------------------------
extern "C" void kernel_launch(void* const* d_in, const int* in_sizes, int n_in,
                              void* d_out, int out_size) {
    const float* x        = (const float*)d_in[0];
    const float* ex       = (const float*)d_in[1];
    const int*   labels   = (const int*)d_in[2];
    const float* beta_raw = (const float*)d_in[3];
    float* out = (float*)d_out;

    const int B  = in_sizes[0] / DD;
    const int NE = in_sizes[1] / DD;

    const int prep_blocks = (NE_PAD + MAXB) / 32;   // 1596
    prep_kernel<<<prep_blocks, 256>>>(x, ex, beta_raw, B, NE);

    static int smem_set = 0;
    if (!smem_set) {
        cudaFuncSetAttribute(exemplar_mma_kernel,
                             cudaFuncAttributeMaxDynamicSharedMemorySize, SM_TOT);
        smem_set = 1;
    }
    dim3 grid(GCOLS, (B + TM - 1) / TM);            // 37 x 8
    exemplar_mma_kernel<<<grid, 256, SM_TOT>>>(B, NE);

    survivor_finalize_kernel<<<148, 256>>>(x, ex, labels, out, B, NE, out_size);
}